// round 16
// baseline (speedup 1.0000x reference)
#include <cuda_runtime.h>
#include <cuda_bf16.h>

// NADE collapse (x is exactly binary; reference scan resets carry to c):
//   out[i,0] = sigmoid(S0[0])
//   out[i,d] = x[i,d-1] ? sigmoid(S1[d]) : sigmoid(S0[d])   (d >= 1)
//   S0[d] = sum_h sigmoid(c[h])            * (V[d,h] + b[d])
//   S1[d] = sum_h sigmoid(W[h,d-1] + c[h]) * (V[d,h] + b[d])
// Table packed as T[d] = {P0[d], P1[d]-P0[d]}; main: out = fma(xprev, diff, P0).
// d==0 has diff=0 so any finite xprev yields P0[0].
//
// Schedule: FULL OVERLAP (R13) + COALESCED tables (R14 mechanism, 9KB tile).
//  - tables fires cudaTriggerProgrammaticLaunchCompletion() first, so the
//    PSS-attributed main runs concurrently with it.
//  - tables stages W through a small smem tile (4 passes x 256 rows): each
//    warp load instruction touches 4 sectors instead of 32 -> no L1tex storm
//    to interfere with main's streaming loads (the R13 failure mode).
//  - main gates g_T reads on monotone g_done (leader acquire + barrier);
//    instant on graph replays; g_T rewrites are bit-identical (benign race).

#define D_DIM  784
#define H_DIM  1024
#define NTBLK  196               // table blocks (= D_DIM / 4)
#define CHUNK2 6422528           // 8192 rows * 784: stride between the 2 chunks
#define NQ2    1605632           // float4s per chunk (= main thread count)

__device__ __align__(16) float2 g_T[D_DIM];   // {P0, P1-P0}
__device__ int g_done = 0;                    // monotone ready counter

__device__ __forceinline__ float tanh_fast(float v) {
    float y;
    asm("tanh.approx.f32 %0, %1;" : "=f"(y) : "f"(v));
    return y;
}
__device__ __forceinline__ float sigmoid_tanh(float v) {
    return fmaf(tanh_fast(0.5f * v), 0.5f, 0.5f);
}
__device__ __forceinline__ int ld_acquire(const int* p) {
    int v;
    asm volatile("ld.global.acquire.gpu.b32 %0, [%1];" : "=r"(v) : "l"(p));
    return v;
}

// ---------------------------------------------------------------------------
// Kernel 1: table build, coalesced via small smem tile. 196 blocks; block j
// owns d in [4j, 4j+4). 4 passes of 256 h-rows:
//   load pass: idx = it*256+tid, hl = idx>>3, cc = idx&7 -> warp covers
//   4 rows x 32B contiguous (4 sectors/instruction).
//   compute:  h = 256p + tid; V/c coalesced; tile reads stride-9 (no bank
//   conflicts). Publishes via fence + atomicAdd(g_done).
// ---------------------------------------------------------------------------
__global__ void __launch_bounds__(256) nade_tables(const float* __restrict__ V,
                                                   const float* __restrict__ b,
                                                   const float* __restrict__ W,
                                                   const float* __restrict__ c) {
    // Let the dependent main kernel launch NOW — full overlap.
    cudaTriggerProgrammaticLaunchCompletion();

    __shared__ float tile[256][9];    // 9.2KB: W rows [256p,256p+256) x 8 cols
    __shared__ float sm[8][8];

    const int j    = blockIdx.x;
    const int tid  = threadIdx.x;
    const int base = 4 * j - 4;       // first staged W column

    const float4 b4 = __ldg(reinterpret_cast<const float4*>(b + 4 * j));
    const float bd[4] = {b4.x, b4.y, b4.z, b4.w};

    float s0[4] = {0.f, 0.f, 0.f, 0.f};
    float s1[4] = {0.f, 0.f, 0.f, 0.f};

    #pragma unroll
    for (int p = 0; p < 4; p++) {
        // ---- stage W rows [256p, 256p+256) x cols [base, base+8) ----
        #pragma unroll
        for (int it = 0; it < 8; it++) {
            const int idx = it * 256 + tid;       // 0..2047
            const int hl  = idx >> 3;             // local row 0..255
            const int cc  = idx & 7;
            const int col = base + cc;
            tile[hl][cc] = (col >= 0) ? W[(p * 256 + hl) * D_DIM + col] : 0.0f;
        }
        __syncthreads();

        // ---- accumulate: h = 256p + tid ----
        const int h = p * 256 + tid;
        const float ch  = __ldg(&c[h]);
        const float sch = sigmoid_tanh(ch);
        #pragma unroll
        for (int k = 0; k < 4; k++) {
            const float vb = __ldg(&V[(4 * j + k) * H_DIM + h]) + bd[k];
            s0[k] = fmaf(sch, vb, s0[k]);
            // W[h][4j+k-1] = tile[tid][k+3]
            s1[k] = fmaf(sigmoid_tanh(tile[tid][k + 3] + ch), vb, s1[k]);
        }
        __syncthreads();
    }

    // ---- block reduce 8 values (256 -> 1 each) ----
    #pragma unroll
    for (int off = 16; off > 0; off >>= 1) {
        #pragma unroll
        for (int k = 0; k < 4; k++) {
            s0[k] += __shfl_down_sync(0xFFFFFFFFu, s0[k], off);
            s1[k] += __shfl_down_sync(0xFFFFFFFFu, s1[k], off);
        }
    }
    const int warp = tid >> 5, lane = tid & 31;
    if (lane == 0) {
        #pragma unroll
        for (int k = 0; k < 4; k++) {
            sm[warp][k]     = s0[k];
            sm[warp][4 + k] = s1[k];
        }
    }
    __syncthreads();

    if (tid == 0) {
        #pragma unroll
        for (int k = 0; k < 4; k++) {
            float a0 = 0.f, a1 = 0.f;
            #pragma unroll
            for (int wq = 0; wq < 8; wq++) {
                a0 += sm[wq][k];
                a1 += sm[wq][4 + k];
            }
            const int d = 4 * j + k;
            const float p0 = sigmoid_tanh(a0);
            const float diff = (d > 0) ? (sigmoid_tanh(a1) - p0) : 0.f;
            g_T[d] = make_float2(p0, diff);
        }
        __threadfence();
        atomicAdd(&g_done, 1);
    }
}

// ---------------------------------------------------------------------------
// Kernel 2: streaming select, 2 chunks per thread at flat stride CHUNK2
// (a multiple of D_DIM: both chunks share d0 and the lane structure).
// ~32 regs -> high occupancy. Flag gate instead of GridDependencySynchronize
// (which would serialize against the concurrently-running tables).
// Grid exact: 1,605,632 threads = 6272 blocks x 256.
// ---------------------------------------------------------------------------
__global__ void __launch_bounds__(256) nade_main(const float* __restrict__ x,
                                                 float* __restrict__ out) {
    const int q  = blockIdx.x * 256 + threadIdx.x;   // [0, NQ2)
    const int e0 = q << 2;                           // flat index, multiple of 4
    const int i  = e0 / D_DIM;
    const int d0 = e0 - i * D_DIM;                   // 0..780, multiple of 4

    // Independent work first: x loads + prev fixups (hides the flag wait).
    const float4 xv0 = *reinterpret_cast<const float4*>(x + e0);
    const float4 xv1 = *reinterpret_cast<const float4*>(x + e0 + CHUNK2);

    float p0 = __shfl_up_sync(0xFFFFFFFFu, xv0.w, 1);
    float p1 = __shfl_up_sync(0xFFFFFFFFu, xv1.w, 1);
    if (((threadIdx.x & 31) == 0) && (d0 != 0)) {
        p0 = x[e0 - 1];
        p1 = x[e0 + CHUNK2 - 1];
    }
    // d0 == 0: T[0].diff == 0, prev value irrelevant (finite).

    // Leader-acquire gate: instant on graph replays (g_done monotone; g_T
    // recomputed bit-identically each call -> same-value races are benign).
    if (threadIdx.x == 0) {
        if (ld_acquire(&g_done) < NTBLK) {
            while (ld_acquire(&g_done) < NTBLK) {
                __nanosleep(128);
            }
        }
    }
    __syncthreads();

    const float4 ta = *reinterpret_cast<const float4*>(&g_T[d0]);      // {P0,df}[d0], {P0,df}[d0+1]
    const float4 tb = *reinterpret_cast<const float4*>(&g_T[d0 + 2]);

    float4 o;
    o.x = fmaf(p0,    ta.y, ta.x);
    o.y = fmaf(xv0.x, ta.w, ta.z);
    o.z = fmaf(xv0.y, tb.y, tb.x);
    o.w = fmaf(xv0.z, tb.w, tb.z);
    __stcs(reinterpret_cast<float4*>(out + e0), o);

    o.x = fmaf(p1,    ta.y, ta.x);
    o.y = fmaf(xv1.x, ta.w, ta.z);
    o.z = fmaf(xv1.y, tb.y, tb.x);
    o.w = fmaf(xv1.z, tb.w, tb.z);
    __stcs(reinterpret_cast<float4*>(out + e0 + CHUNK2), o);
}

// ---------------------------------------------------------------------------
extern "C" void kernel_launch(void* const* d_in, const int* in_sizes, int n_in,
                              void* d_out, int out_size) {
    const float* x = (const float*)d_in[0];
    const float* V = (const float*)d_in[1];
    const float* b = (const float*)d_in[2];
    const float* W = (const float*)d_in[3];
    const float* c = (const float*)d_in[4];
    float* out = (float*)d_out;

    nade_tables<<<NTBLK, 256>>>(V, b, W, c);

    cudaLaunchConfig_t cfg = {};
    cfg.gridDim  = dim3(NQ2 / 256);       // 6272
    cfg.blockDim = dim3(256);
    cfg.dynamicSmemBytes = 0;
    cfg.stream = 0;
    cudaLaunchAttribute attr[1];
    attr[0].id = cudaLaunchAttributeProgrammaticStreamSerialization;
    attr[0].val.programmaticStreamSerializationAllowed = 1;
    cfg.attrs = attr;
    cfg.numAttrs = 1;
    cudaLaunchKernelEx(&cfg, nade_main, x, out);
}

// round 17
// speedup vs baseline: 1.0191x; 1.0191x over previous
#include <cuda_runtime.h>
#include <cuda_bf16.h>

// NADE collapse (x is exactly binary; reference scan resets carry to c):
//   out[i,0] = sigmoid(S0[0])
//   out[i,d] = x[i,d-1] ? sigmoid(S1[d]) : sigmoid(S0[d])   (d >= 1)
//   S0[d] = sum_h sigmoid(c[h])            * (V[d,h] + b[d])
//   S1[d] = sum_h sigmoid(W[h,d-1] + c[h]) * (V[d,h] + b[d])
// Table packed as T[d] = {P0[d], P1[d]-P0[d]}; main: out = fma(xprev, diff, P0).
// d==0 has diff=0 so any finite xprev yields P0[0].
//
// PARTIAL-OVERLAP schedule (the one untested point between serial and full
// overlap): tables fires cudaTriggerProgrammaticLaunchCompletion() as its
// FIRST statement -> main launches immediately and its wave-1 blocks run
// their pre-sync prologue (index math + x float4 loads, ~9.7MB prefetch)
// concurrently with tables; then cudaGridDependencySynchronize() blocks until
// the tables GRID fully completes (automatic correctness, no flags). Main's
// store stream never overlaps tables, so the R13/R16 bandwidth-contention
// failure mode is avoided.

#define D_DIM 784
#define H_DIM 1024
#define CHUNK 3211264            // 4096 rows * 784: flat-element stride between chunks
#define NQ    802816             // float4s per chunk (= thread count of nade_main)

__device__ __align__(16) float2 g_T[D_DIM];   // {P0, P1-P0}

__device__ __forceinline__ float tanh_fast(float v) {
    float y;
    asm("tanh.approx.f32 %0, %1;" : "=f"(y) : "f"(v));
    return y;
}
__device__ __forceinline__ float sigmoid_tanh(float v) {
    return fmaf(tanh_fast(0.5f * v), 0.5f, 0.5f);
}

// ---------------------------------------------------------------------------
// Kernel 1: table build. 196 blocks; block j owns d in [4j, 4j+4).
// Thread owns 4 consecutive h. W columns [4j-4, 4j+4) read as two aligned
// float4s per h-row. Trigger at TOP: releases main's launch immediately.
// ---------------------------------------------------------------------------
__global__ void __launch_bounds__(256) nade_tables(const float* __restrict__ V,
                                                   const float* __restrict__ b,
                                                   const float* __restrict__ W,
                                                   const float* __restrict__ c) {
    cudaTriggerProgrammaticLaunchCompletion();

    const int j   = blockIdx.x;
    const int tid = threadIdx.x;
    const int h0  = tid * 4;

    const float4 c4 = *reinterpret_cast<const float4*>(c + h0);
    const float sc0 = sigmoid_tanh(c4.x);
    const float sc1 = sigmoid_tanh(c4.y);
    const float sc2 = sigmoid_tanh(c4.z);
    const float sc3 = sigmoid_tanh(c4.w);

    const float4 b4 = __ldg(reinterpret_cast<const float4*>(b + 4 * j));
    float bd[4] = {b4.x, b4.y, b4.z, b4.w};

    // W cols [4j-4, 4j+4): w[hh][idx] = W[h0+hh][4j-4+idx], idx 0..7.
    // Needed: wcol(k) = 4j+k-1 -> idx k+3 (k=0..3). j==0,k==0 unused (diff=0).
    float w[4][8];
    const int base = 4 * j - 4;
    #pragma unroll
    for (int hh = 0; hh < 4; hh++) {
        const float* wr = W + (h0 + hh) * D_DIM;
        if (j > 0) {
            const float4 a = __ldg(reinterpret_cast<const float4*>(wr + base));
            w[hh][0] = a.x; w[hh][1] = a.y; w[hh][2] = a.z; w[hh][3] = a.w;
        } else {
            w[hh][0] = 0.f; w[hh][1] = 0.f; w[hh][2] = 0.f; w[hh][3] = 0.f;
        }
        const float4 q = __ldg(reinterpret_cast<const float4*>(wr + base + 4));
        w[hh][4] = q.x; w[hh][5] = q.y; w[hh][6] = q.z; w[hh][7] = q.w;
    }

    float s0[4], s1[4];
    #pragma unroll
    for (int k = 0; k < 4; k++) {
        const float4 v4 = __ldg(reinterpret_cast<const float4*>(V + (4 * j + k) * H_DIM + h0));
        const float vb0 = v4.x + bd[k];
        const float vb1 = v4.y + bd[k];
        const float vb2 = v4.z + bd[k];
        const float vb3 = v4.w + bd[k];
        s0[k] = sc0 * vb0 + sc1 * vb1 + sc2 * vb2 + sc3 * vb3;
        float t;
        t  = sigmoid_tanh(w[0][k + 3] + c4.x) * vb0;
        t += sigmoid_tanh(w[1][k + 3] + c4.y) * vb1;
        t += sigmoid_tanh(w[2][k + 3] + c4.z) * vb2;
        t += sigmoid_tanh(w[3][k + 3] + c4.w) * vb3;
        s1[k] = t;
    }

    // block reduce 8 values (256 -> 1 each)
    #pragma unroll
    for (int off = 16; off > 0; off >>= 1) {
        #pragma unroll
        for (int k = 0; k < 4; k++) {
            s0[k] += __shfl_down_sync(0xFFFFFFFFu, s0[k], off);
            s1[k] += __shfl_down_sync(0xFFFFFFFFu, s1[k], off);
        }
    }
    __shared__ float sm[8][8];
    const int warp = tid >> 5, lane = tid & 31;
    if (lane == 0) {
        #pragma unroll
        for (int k = 0; k < 4; k++) {
            sm[warp][k]     = s0[k];
            sm[warp][4 + k] = s1[k];
        }
    }
    __syncthreads();
    if (tid < 4) {
        float a0 = 0.f, a1 = 0.f;
        #pragma unroll
        for (int wq = 0; wq < 8; wq++) {
            a0 += sm[wq][tid];
            a1 += sm[wq][4 + tid];
        }
        const int d = 4 * j + tid;
        const float p0 = sigmoid_tanh(a0);
        const float diff = (d > 0) ? (sigmoid_tanh(a1) - p0) : 0.f;
        g_T[d] = make_float2(p0, diff);
    }
}

// ---------------------------------------------------------------------------
// Kernel 2: streaming select, 4 chunks per thread at flat stride CHUNK
// (a multiple of D_DIM, so all chunks share d0 and the same lane/row-boundary
// structure). Pre-sync prologue (index math + x loads) overlaps tables;
// cudaGridDependencySynchronize guarantees the tables grid completed before
// the g_T reads. Grid exact: 802,816 threads = 3136 x 256.
// ---------------------------------------------------------------------------
__global__ void __launch_bounds__(256) nade_main(const float* __restrict__ x,
                                                 float* __restrict__ out) {
    const int q  = blockIdx.x * 256 + threadIdx.x;   // [0, NQ)
    const int e0 = q << 2;                           // flat index, multiple of 4
    const int i  = e0 / D_DIM;
    const int d0 = e0 - i * D_DIM;                   // 0..780, multiple of 4

    // Pre-sync prologue: independent of g_T, overlaps the tables kernel.
    const float4 xv0 = *reinterpret_cast<const float4*>(x + e0);
    const float4 xv1 = *reinterpret_cast<const float4*>(x + e0 + CHUNK);
    const float4 xv2 = *reinterpret_cast<const float4*>(x + e0 + 2 * CHUNK);
    const float4 xv3 = *reinterpret_cast<const float4*>(x + e0 + 3 * CHUNK);

    float p0 = __shfl_up_sync(0xFFFFFFFFu, xv0.w, 1);
    float p1 = __shfl_up_sync(0xFFFFFFFFu, xv1.w, 1);
    float p2 = __shfl_up_sync(0xFFFFFFFFu, xv2.w, 1);
    float p3 = __shfl_up_sync(0xFFFFFFFFu, xv3.w, 1);
    if (((threadIdx.x & 31) == 0) && (d0 != 0)) {
        p0 = __ldg(&x[e0 - 1]);
        p1 = __ldg(&x[e0 + CHUNK - 1]);
        p2 = __ldg(&x[e0 + 2 * CHUNK - 1]);
        p3 = __ldg(&x[e0 + 3 * CHUNK - 1]);
    }
    // d0 == 0: T[0].diff == 0, prev value irrelevant (finite).

    // Wait for the FULL tables grid to complete (automatic correctness).
    cudaGridDependencySynchronize();

    const float4 ta = *reinterpret_cast<const float4*>(&g_T[d0]);      // {P0,df}[d0], {P0,df}[d0+1]
    const float4 tb = *reinterpret_cast<const float4*>(&g_T[d0 + 2]);

    float4 o;
    o.x = fmaf(p0,    ta.y, ta.x);
    o.y = fmaf(xv0.x, ta.w, ta.z);
    o.z = fmaf(xv0.y, tb.y, tb.x);
    o.w = fmaf(xv0.z, tb.w, tb.z);
    __stcs(reinterpret_cast<float4*>(out + e0), o);

    o.x = fmaf(p1,    ta.y, ta.x);
    o.y = fmaf(xv1.x, ta.w, ta.z);
    o.z = fmaf(xv1.y, tb.y, tb.x);
    o.w = fmaf(xv1.z, tb.w, tb.z);
    __stcs(reinterpret_cast<float4*>(out + e0 + CHUNK), o);

    o.x = fmaf(p2,    ta.y, ta.x);
    o.y = fmaf(xv2.x, ta.w, ta.z);
    o.z = fmaf(xv2.y, tb.y, tb.x);
    o.w = fmaf(xv2.z, tb.w, tb.z);
    __stcs(reinterpret_cast<float4*>(out + e0 + 2 * CHUNK), o);

    o.x = fmaf(p3,    ta.y, ta.x);
    o.y = fmaf(xv3.x, ta.w, ta.z);
    o.z = fmaf(xv3.y, tb.y, tb.x);
    o.w = fmaf(xv3.z, tb.w, tb.z);
    __stcs(reinterpret_cast<float4*>(out + e0 + 3 * CHUNK), o);
}

// ---------------------------------------------------------------------------
extern "C" void kernel_launch(void* const* d_in, const int* in_sizes, int n_in,
                              void* d_out, int out_size) {
    const float* x = (const float*)d_in[0];
    const float* V = (const float*)d_in[1];
    const float* b = (const float*)d_in[2];
    const float* W = (const float*)d_in[3];
    const float* c = (const float*)d_in[4];
    float* out = (float*)d_out;

    nade_tables<<<D_DIM / 4, 256>>>(V, b, W, c);

    cudaLaunchConfig_t cfg = {};
    cfg.gridDim  = dim3(NQ / 256);        // 3136
    cfg.blockDim = dim3(256);
    cfg.dynamicSmemBytes = 0;
    cfg.stream = 0;
    cudaLaunchAttribute attr[1];
    attr[0].id = cudaLaunchAttributeProgrammaticStreamSerialization;
    attr[0].val.programmaticStreamSerializationAllowed = 1;
    cfg.attrs = attr;
    cfg.numAttrs = 1;
    cudaLaunchKernelEx(&cfg, nade_main, x, out);
}